// round 17
// baseline (speedup 1.0000x reference)
#include <cuda_runtime.h>
#include <stdint.h>

#define T_SEQ 2048
#define BATCH 64
#define INPUT 16
#define HEADS 8
#define HID   64
#define GATES 256   // 4*HID
#define XW_STRIDE 18  // floats per sh_xw row (72B: 8B-aligned, 2-way-conflict max)

#define FMA2(acc, a, b) \
    asm("fma.rn.f32x2 %0, %1, %2, %0;" : "+l"(acc) : "l"(a), "l"(b))
#define ADD2(d, a, b) \
    asm("add.rn.f32x2 %0, %1, %2;" : "=l"(d) : "l"(a), "l"(b))
#define PACK2(d, lo, hi) \
    asm("mov.b64 %0, {%1, %2};" : "=l"(d) : "f"(lo), "f"(hi))
#define UNPACK2(lo, hi, s) \
    asm("mov.b64 {%0, %1}, %2;" : "=f"(lo), "=f"(hi) : "l"(s))

__device__ __forceinline__ float tanh_hw(float x) {
    float r;
    asm("tanh.approx.f32 %0, %1;" : "=f"(r) : "f"(x));
    return r;
}
__device__ __forceinline__ float sigmoid_hw(float x) {
    return fmaf(0.5f, tanh_hw(0.5f * x), 0.5f);
}

// Pre-fill outputs: out[t,b,h] = b_lin[h]; lstm_out = 0. (d_out is poisoned.)
__global__ __launch_bounds__(256)
void init_out_kernel(const float* __restrict__ b_lin, float* __restrict__ o) {
    const int idx = blockIdx.x * 256 + threadIdx.x;
    const int n_out = T_SEQ * BATCH * HEADS;
    const int n_tot = n_out + T_SEQ * BATCH * HID;
    if (idx < n_out)      o[idx] = b_lin[idx & 7];
    else if (idx < n_tot) o[idx] = 0.0f;
}

// One CTA per (head, batch-pair): 2 chains, 512 threads.
// Thread (g = tid&255, s = tid>>8) owns HALF of gate row g (k in [s*32,s*32+32)).
// ~60 regs/thread -> 2 CTAs/SM -> 8 warps/SMSP (2x latency hiding vs R14).
__global__ __launch_bounds__(512, 2)
void lstm_chain2_kernel(const float* __restrict__ x,
                        const float* __restrict__ W_ih,
                        const float* __restrict__ W_hh,
                        const float* __restrict__ b_ih,
                        const float* __restrict__ b_hh,
                        const float* __restrict__ W_lin,
                        float* __restrict__ out,       // (T,B,H)
                        float* __restrict__ lstm_out)  // (T,B,HID)
{
    const int h   = blockIdx.x & 7;
    const int b0  = (blockIdx.x >> 3) * 2;
    const int tid = threadIdx.x;
    const int g   = tid & 255;   // gate row
    const int s   = tid >> 8;    // half-index: which 32 of the 64 k's

    __shared__ __align__(16) float sh_xw[GATES * XW_STRIDE]; // W_ih rows, head h
    __shared__ __align__(16) uint64_t sh_p0[GATES];          // partials chain 0
    __shared__ __align__(16) uint64_t sh_p1[GATES];          // partials chain 1
    __shared__ float sh_act[2][GATES];
    __shared__ __align__(16) float sh_h[2][2][HID];          // [parity][chain][k]
    __shared__ __align__(16) float sh_x[2][2][INPUT];        // [buf][chain][i]

    // Stage W_ih rows for this head into smem (stride 18 floats).
    for (int i = tid; i < GATES * INPUT; i += 512) {
        const int r = i >> 4, ci = i & 15;
        sh_xw[r * XW_STRIDE + ci] = W_ih[(h * GATES + r) * INPUT + ci];
    }
    // x[0], x[1] for both chains
    if (tid < 64) {
        const int buf = tid >> 5, ch = (tid >> 4) & 1, i = tid & 15;
        sh_x[buf][ch][i] = x[(buf * BATCH + b0 + ch) * INPUT + i];
    }
    if (tid < 128) sh_h[0][tid >> 6][tid & 63] = 0.0f;

    // Half-row of W_hh in registers (16 u64 = 32 regs).
    uint64_t w[HID / 4];
    {
        const float* wr = W_hh + (h * GATES + g) * HID + s * 32;
#pragma unroll
        for (int q = 0; q < HID / 4; q++) PACK2(w[q], wr[2 * q], wr[2 * q + 1]);
    }
    const float bias = b_ih[h * GATES + g] + b_hh[h * GATES + g];
    uint64_t bias2; PACK2(bias2, bias, 0.0f);

    // Epilogue role (threads 0-127): ech = tid>>6, ek = tid&63.
    const int  ek  = tid & 63;
    const int  ech = (tid >> 6) & 1;
    const float wl = (tid < 128) ? W_lin[h * HID + ek] : 0.0f;
    float c = 0.0f;

    const int gate_type = g >> 6;  // warp-uniform for s==0 warps

    __syncthreads();

    // Initial xacc (t=0), held by s==1 threads; includes bias.
    uint64_t xacc0 = 0ull, xacc1 = 0ull;
    if (s) {
        xacc0 = bias2; xacc1 = bias2;
        const uint64_t* xwr = (const uint64_t*)(sh_xw + g * XW_STRIDE);
        const ulonglong2* xA = (const ulonglong2*)sh_x[0][0];
        const ulonglong2* xB = (const ulonglong2*)sh_x[0][1];
#pragma unroll
        for (int q = 0; q < INPUT / 4; q++) {
            const uint64_t w0 = xwr[2 * q], w1 = xwr[2 * q + 1];
            ulonglong2 vA = xA[q], vB = xB[q];
            FMA2(xacc0, w0, vA.x); FMA2(xacc0, w1, vA.y);
            FMA2(xacc1, w0, vB.x); FMA2(xacc1, w1, vB.y);
        }
    }

    float* out_p  = out + (size_t)(b0 + ech) * HEADS + h;
    float* lstm_p = lstm_out + (size_t)(b0 + ech) * HID + ek;

#pragma unroll 1
    for (int t = 0; t < T_SEQ; t++) {
        const int hp = t & 1;

        // Stage x_{t+2} (threads 256-287), hidden under phase A.
        float xreg = 0.0f;
        if (tid >= 256 && tid < 288 && t + 2 < T_SEQ)
            xreg = x[((t + 2) * BATCH + b0 + ((tid >> 4) & 1)) * INPUT + (tid & 15)];

        // ---- Phase A: half h-dot for both chains ----
        uint64_t p0 = s ? xacc0 : 0ull;
        uint64_t p1 = s ? xacc1 : 0ull;
        const ulonglong2* hA = (const ulonglong2*)&sh_h[hp][0][s * 32];
        const ulonglong2* hB = (const ulonglong2*)&sh_h[hp][1][s * 32];
#pragma unroll
        for (int q = 0; q < 8; q++) {
            ulonglong2 vA = hA[q], vB = hB[q];
            FMA2(p0, w[2 * q],     vA.x);
            FMA2(p0, w[2 * q + 1], vA.y);
            FMA2(p1, w[2 * q],     vB.x);
            FMA2(p1, w[2 * q + 1], vB.y);
        }
        if (s) { sh_p0[g] = p0; sh_p1[g] = p1; }
        __syncthreads();   // B1: partials visible

        // ---- Phase B: s0 combine+activate; s1 compute xacc_{t+1} ----
        float a0, a1;
        if (s == 0) {
            uint64_t q0 = sh_p0[g], q1 = sh_p1[g];
            ADD2(q0, q0, p0);
            ADD2(q1, q1, p1);
            float lo0, hi0, lo1, hi1;
            UNPACK2(lo0, hi0, q0);
            UNPACK2(lo1, hi1, q1);
            const float z0 = lo0 + hi0, z1 = lo1 + hi1;
            if (gate_type == 2) { a0 = tanh_hw(z0);    a1 = tanh_hw(z1);    }
            else                { a0 = sigmoid_hw(z0); a1 = sigmoid_hw(z1); }
            sh_act[0][g] = a0;
            sh_act[1][g] = a1;
        } else {
            const int xb = (t + 1) & 1;
            xacc0 = bias2; xacc1 = bias2;
            const uint64_t* xwr = (const uint64_t*)(sh_xw + g * XW_STRIDE);
            const ulonglong2* xA = (const ulonglong2*)sh_x[xb][0];
            const ulonglong2* xB = (const ulonglong2*)sh_x[xb][1];
#pragma unroll
            for (int q = 0; q < INPUT / 4; q++) {
                const uint64_t w0 = xwr[2 * q], w1 = xwr[2 * q + 1];
                ulonglong2 vA = xA[q], vB = xB[q];
                FMA2(xacc0, w0, vA.x); FMA2(xacc0, w1, vA.y);
                FMA2(xacc1, w0, vB.x); FMA2(xacc1, w1, vB.y);
            }
        }
        __syncthreads();   // B2: acts visible

        // ---- Phase C: epilogue (threads 0-127) + x staging ----
        if (tid < 128) {
            // Own-value reuse: tid<64 computed row ek (= i-gate, chain a0);
            // tid in [64,128) computed row 64+ek (= f-gate, chain a1).
            float iv, fv;
            if (ech == 0) { iv = a0; fv = sh_act[0][HID + ek]; }
            else          { fv = a1; iv = sh_act[1][ek]; }
            const float gv = sh_act[ech][2 * HID + ek];
            const float ov = sh_act[ech][3 * HID + ek];
            c = fmaf(fv, c, iv * gv);
            const float hv = ov * tanh_hw(c);
            sh_h[1 - hp][ech][ek] = hv;
            atomicAdd(out_p,  hv * wl);   // RED.ADD.F32, fire-and-forget
            atomicAdd(lstm_p, hv);        // RED.ADD.F32
        }
        if (tid >= 256 && tid < 288)
            sh_x[t & 1][(tid >> 4) & 1][tid & 15] = xreg;
        __syncthreads();   // B3: sh_h / sh_x settled for next step

        out_p  += BATCH * HEADS;
        lstm_p += BATCH * HID;
    }
}

extern "C" void kernel_launch(void* const* d_in, const int* in_sizes, int n_in,
                              void* d_out, int out_size) {
    const float* x     = (const float*)d_in[0];  // (T,B,I)
    const float* W_ih  = (const float*)d_in[1];  // (H,4h,I)
    const float* W_hh  = (const float*)d_in[2];  // (H,4h,h)
    const float* b_ih  = (const float*)d_in[3];  // (H,4h)
    const float* b_hh  = (const float*)d_in[4];  // (H,4h)
    const float* W_lin = (const float*)d_in[5];  // (H,h)
    const float* b_lin = (const float*)d_in[6];  // (H,)

    float* out      = (float*)d_out;                          // (T,B,H)
    float* lstm_out = out + (size_t)T_SEQ * BATCH * HEADS;    // (T,B,hid)

    const int n_tot = T_SEQ * BATCH * (HEADS + HID);
    init_out_kernel<<<(n_tot + 255) / 256, 256>>>(b_lin, (float*)d_out);
    lstm_chain2_kernel<<<BATCH * HEADS / 2, 512>>>(x, W_ih, W_hh, b_ih, b_hh,
                                                   W_lin, out, lstm_out);
}